// round 15
// baseline (speedup 1.0000x reference)
#include <cuda_runtime.h>
#include <cstdint>

#define HH 1024
#define WW 1024
#define BATCH 16
#define NIMG (HH*WW)
#define NTEN (BATCH*NIMG)
#define RS 64                       // output rows per warp sweep
#define NBAND (HH/RS)               // 16
#define DEPTH 8                     // ring rows (4 commit groups of 2 rows)
#define FULLM 0xffffffffu
#define TOTW 4096                   // 8 strips * 16 bands * 32 images

__device__ float g_buf0[2*NTEN];
__device__ float g_buf1[2*NTEN];
__device__ double g_pp[TOTW];
__device__ double g_ps[TOTW];

__device__ __forceinline__ float PINF() { return __int_as_float(0x7f800000); }
__device__ __forceinline__ float NINF() { return __int_as_float(0xff800000); }
__device__ __forceinline__ float min3(float a, float b, float c) { return fminf(a, fminf(b, c)); }
__device__ __forceinline__ float max3(float a, float b, float c) { return fmaxf(a, fmaxf(b, c)); }

__device__ __forceinline__ uint32_t saddr(const void* p) {
    return (uint32_t)__cvta_generic_to_shared(p);
}
__device__ __forceinline__ void cp16(uint32_t s, const void* g) {
    asm volatile("cp.async.cg.shared.global [%0], [%1], 16;" :: "r"(s), "l"(g));
}
__device__ __forceinline__ void cp8(uint32_t s, const void* g) {
    asm volatile("cp.async.ca.shared.global [%0], [%1], 8;" :: "r"(s), "l"(g));
}
__device__ __forceinline__ void cp_commit() {
    asm volatile("cp.async.commit_group;" ::: "memory");
}
template<int N>
__device__ __forceinline__ void cp_wait() {
    asm volatile("cp.async.wait_group %0;" :: "n"(N) : "memory");
}

// Rolling state for the separable 3x3 min-pool -> 3x3 max-pool pipeline.
struct St {
    float hA[4], hB[4];      // horizontal-min rows (rr-2, rr-1)
    float gA[4], gB[4];      // vertical-max candidate rows
    float mC[4];             // min-pool value at the output row (unmasked)
    float hlA, hlB, hrA, hrB;// edge-lane horizontal mins (left/right halo)
    float4 xA, xB;           // input delay line (x at output row)
};

__device__ __forceinline__ void st_init(St& S) {
    #pragma unroll
    for (int j = 0; j < 4; j++) {
        S.hA[j] = PINF(); S.hB[j] = PINF();
        S.gA[j] = NINF(); S.gB[j] = NINF();
        S.mC[j] = 0.f;
    }
    S.hlA = PINF(); S.hlB = PINF(); S.hrA = PINF(); S.hrB = PINF();
    S.xA = make_float4(0.f, 0.f, 0.f, 0.f);
    S.xB = S.xA;
}

// Process one input row; emit skeleton output for row rr-2.
template<bool VEDGE>
__device__ __forceinline__ float4 advance(St& S, int lane, int rr,
                                          bool leftok, bool rightok,
                                          float4 A, float xl2, float xl1,
                                          float xr0, float xr1)
{
    float xm1 = __shfl_up_sync(FULLM, A.w, 1);
    if (lane == 0) xm1 = xl1;
    float xp4 = __shfl_down_sync(FULLM, A.x, 1);
    if (lane == 31) xp4 = xr0;
    float hC[4];
    hC[0] = min3(xm1, A.x, A.y);  hC[1] = min3(A.x, A.y, A.z);
    hC[2] = min3(A.y, A.z, A.w);  hC[3] = min3(A.z, A.w, xp4);
    float hlC = min3(xl2, xl1, A.x);
    float hrC = min3(A.w, xr0, xr1);

    float m[4], mM[4];
    const bool rvC = (!VEDGE) || (((rr - 1) >= 0) && ((rr - 1) < HH));
    #pragma unroll
    for (int j = 0; j < 4; j++) {
        m[j]  = min3(S.hA[j], S.hB[j], hC[j]);
        mM[j] = rvC ? m[j] : NINF();
    }
    float ml = min3(S.hlA, S.hlB, hlC);
    float mr = min3(S.hrA, S.hrB, hrC);
    float mlM = (leftok  && rvC) ? ml : NINF();
    float mrM = (rightok && rvC) ? mr : NINF();

    float mm1 = __shfl_up_sync(FULLM, mM[3], 1);
    if (lane == 0) mm1 = mlM;
    float mp4 = __shfl_down_sync(FULLM, mM[0], 1);
    if (lane == 31) mp4 = mrM;
    float gC[4];
    gC[0] = max3(mm1,  mM[0], mM[1]);  gC[1] = max3(mM[0], mM[1], mM[2]);
    gC[2] = max3(mM[1], mM[2], mM[3]); gC[3] = max3(mM[2], mM[3], mp4);

    float4 o;
    o.x = fmaxf(S.xA.x - fmaxf(max3(S.gA[0], S.gB[0], gC[0]) - S.mC[0], 0.f), 0.f);
    o.y = fmaxf(S.xA.y - fmaxf(max3(S.gA[1], S.gB[1], gC[1]) - S.mC[1], 0.f), 0.f);
    o.z = fmaxf(S.xA.z - fmaxf(max3(S.gA[2], S.gB[2], gC[2]) - S.mC[2], 0.f), 0.f);
    o.w = fmaxf(S.xA.w - fmaxf(max3(S.gA[3], S.gB[3], gC[3]) - S.mC[3], 0.f), 0.f);

    #pragma unroll
    for (int j = 0; j < 4; j++) {
        S.hA[j] = S.hB[j]; S.hB[j] = hC[j];
        S.gA[j] = S.gB[j]; S.gB[j] = gC[j];
        S.mC[j] = m[j];
    }
    S.hlA = S.hlB; S.hlB = hlC;
    S.hrA = S.hrB; S.hrB = hrC;
    S.xA = S.xB; S.xB = A;
    return o;
}

// Prefetch one row into ring stage s (no commit). CLAMP: clamp row into image
// (edge bands); interior bands skip the clamp entirely.
template<bool CLAMP>
__device__ __forceinline__ void prefetch_row(const float* __restrict__ src, int rr,
                                             int gX, int c0, int lane,
                                             bool leftok, bool rightok,
                                             float4* ringw, float2* hlw, float2* hrw,
                                             int s)
{
    int rc = rr;
    if (CLAMP) rc = rr < 0 ? 0 : (rr > HH - 1 ? HH - 1 : rr);
    const float* rowp = src + (long)rc * WW;
    cp16(saddr(ringw + s * 32 + lane), rowp + gX);
    if (lane == 0 && leftok)   cp8(saddr(hlw + s), rowp + c0 - 2);
    if (lane == 31 && rightok) cp8(saddr(hrw + s), rowp + c0 + 128);
}

// Read ring stage s as (A, hl, hr), masking to +inf outside image (VEDGE only).
template<bool VEDGE>
__device__ __forceinline__ void read_stage(const float4* ringw, const float2* hlw,
                                           const float2* hrw, int s, int rr, int lane,
                                           float4& A, float2& hl, float2& hr)
{
    A  = ringw[s * 32 + lane];
    hl = hlw[s];
    hr = hrw[s];
    if (VEDGE && !((rr >= 0) && (rr < HH))) {
        A  = make_float4(PINF(), PINF(), PINF(), PINF());
        hl = make_float2(PINF(), PINF());
        hr = make_float2(PINF(), PINF());
    }
}

template<bool VEDGE, bool FINAL>
__device__ __forceinline__ void sweep(const float* __restrict__ src,
                                      float* __restrict__ out,
                                      const float* __restrict__ oth,
                                      int c0, int gX, int r0, int lane,
                                      bool leftok, bool rightok,
                                      float4* ringw, float2* hlw, float2* hrw,
                                      float& accp, float& accs)
{
    St S;
    st_init(S);

    // Halo slot defaults (+inf): lane 0 owns hlw, lane 31 owns hrw; slots are
    // only ever read back by the same thread that wrote them (cross-lane halo
    // values reach other lanes via shuffles in advance()).
    if (lane == 0) {
        #pragma unroll
        for (int s = 0; s < DEPTH; s++) hlw[s] = make_float2(PINF(), PINF());
    }
    if (lane == 31) {
        #pragma unroll
        for (int s = 0; s < DEPTH; s++) hrw[s] = make_float2(PINF(), PINF());
    }

    // Fill the ring: rows r0-2 .. r0+5 as 4 pair-groups.
    #pragma unroll
    for (int s = 0; s < DEPTH; s += 2) {
        prefetch_row<VEDGE>(src, r0 - 2 + s,     gX, c0, lane, leftok, rightok, ringw, hlw, hrw, s);
        prefetch_row<VEDGE>(src, r0 - 2 + s + 1, gX, c0, lane, leftok, rightok, ringw, hlw, hrw, s + 1);
        cp_commit();
    }

    // Prologue: rows r0-2 .. r0+1 (2 pairs, no emit).
    #pragma unroll
    for (int k = 0; k < 4; k += 2) {
        cp_wait<3>();
        float4 A0, A1; float2 hl0, hr0, hl1, hr1;
        read_stage<VEDGE>(ringw, hlw, hrw, k,     r0 - 2 + k,     lane, A0, hl0, hr0);
        read_stage<VEDGE>(ringw, hlw, hrw, k + 1, r0 - 1 + k,     lane, A1, hl1, hr1);
        (void)advance<VEDGE>(S, lane, r0 - 2 + k, leftok, rightok, A0, hl0.x, hl0.y, hr0.x, hr0.y);
        (void)advance<VEDGE>(S, lane, r0 - 1 + k, leftok, rightok, A1, hl1.x, hl1.y, hr1.x, hr1.y);
        prefetch_row<VEDGE>(src, r0 - 2 + k + DEPTH,     gX, c0, lane, leftok, rightok, ringw, hlw, hrw, k);
        prefetch_row<VEDGE>(src, r0 - 1 + k + DEPTH,     gX, c0, lane, leftok, rightok, ringw, hlw, hrw, k + 1);
        cp_commit();
    }

    // Main: rows r0+2 .. r0+RS+1 -> emit rows r0 .. r0+RS-1 (pairs).
    #pragma unroll 8
    for (int k = 0; k < RS; k += 2) {
        const int rr = r0 + 2 + k;
        const int s  = (k + 4) & (DEPTH - 1);
        cp_wait<3>();
        float4 A0, A1; float2 hl0, hr0, hl1, hr1;
        read_stage<VEDGE>(ringw, hlw, hrw, s,     rr,     lane, A0, hl0, hr0);
        read_stage<VEDGE>(ringw, hlw, hrw, s + 1, rr + 1, lane, A1, hl1, hr1);
        float4 o0 = advance<VEDGE>(S, lane, rr,     leftok, rightok, A0, hl0.x, hl0.y, hr0.x, hr0.y);
        float4 o1 = advance<VEDGE>(S, lane, rr + 1, leftok, rightok, A1, hl1.x, hl1.y, hr1.x, hr1.y);
        if (FINAL) {
            const float4 v0 = __ldcs((const float4*)(oth + ((long)(r0 + k) * WW + gX)));
            const float4 v1 = __ldcs((const float4*)(oth + ((long)(r0 + k + 1) * WW + gX)));
            accp += o0.x * v0.x + o0.y * v0.y + o0.z * v0.z + o0.w * v0.w;
            accs += o0.x + o0.y + o0.z + o0.w;
            accp += o1.x * v1.x + o1.y * v1.y + o1.z * v1.z + o1.w * v1.w;
            accs += o1.x + o1.y + o1.z + o1.w;
        } else {
            __stcs((float4*)(out + ((long)(r0 + k) * WW + gX)), o0);
            __stcs((float4*)(out + ((long)(r0 + k + 1) * WW + gX)), o1);
        }
        // Refill the pair just consumed.
        prefetch_row<VEDGE>(src, rr + DEPTH,     gX, c0, lane, leftok, rightok, ringw, hlw, hrw, s);
        prefetch_row<VEDGE>(src, rr + 1 + DEPTH, gX, c0, lane, leftok, rightok, ringw, hlw, hrw, s + 1);
        cp_commit();
    }
    cp_wait<0>();
}

template<bool FINAL>
__global__ __launch_bounds__(128, 8)
void skel_kernel(const float* __restrict__ in0, const float* __restrict__ in1,
                 float* __restrict__ dst,
                 const float* __restrict__ oth0, const float* __restrict__ oth1)
{
    __shared__ float4 ring[4][DEPTH * 32];   // 16 KB: [warp][stage*32+lane]
    __shared__ float2 haloL[4][DEPTH];
    __shared__ float2 haloR[4][DEPTH];

    const int lane  = threadIdx.x & 31;
    const int warp  = threadIdx.x >> 5;
    const int strip = blockIdx.y * 4 + warp;      // 0..7 (128 cols each)
    const int band  = blockIdx.x;                 // 0..15
    const int img   = blockIdx.z;                 // 0..31
    const int t = img >> 4;
    const int b = img & 15;

    const float* src = (t == 0 ? in0 : in1) + (size_t)b * NIMG;
    const float* oth = FINAL ? ((t == 0 ? oth0 : oth1) + (size_t)b * NIMG) : (const float*)0;
    float* out = FINAL ? (float*)0 : dst + (size_t)t * NTEN + (size_t)b * NIMG;

    const int c0 = strip * 128;
    const int gX = c0 + 4 * lane;
    const int r0 = band * RS;
    const bool leftok  = (strip > 0);
    const bool rightok = (strip < 7);

    float accp = 0.f, accs = 0.f;
    if (band == 0 || band == NBAND - 1)
        sweep<true,  FINAL>(src, out, oth, c0, gX, r0, lane, leftok, rightok,
                            ring[warp], haloL[warp], haloR[warp], accp, accs);
    else
        sweep<false, FINAL>(src, out, oth, c0, gX, r0, lane, leftok, rightok,
                            ring[warp], haloL[warp], haloR[warp], accp, accs);

    if (FINAL) {
        double p = (double)accp, s = (double)accs;
        #pragma unroll
        for (int off = 16; off; off >>= 1) {
            p += __shfl_down_sync(FULLM, p, off);
            s += __shfl_down_sync(FULLM, s, off);
        }
        if (lane == 0) {
            const int wid = (img * NBAND + band) * 8 + strip;
            g_pp[wid] = p;
            g_ps[wid] = s;
        }
    }
}

__global__ void finish_kernel(float* __restrict__ out)
{
    __shared__ double sp0[8], ss0[8], sp1[8], ss1[8];
    double a0 = 0, c0 = 0, a1 = 0, c1 = 0;
    for (int i = threadIdx.x; i < TOTW; i += 256) {
        const int img = i >> 7;     // 128 warps per image
        double pp = g_pp[i], ss = g_ps[i];
        if ((img >> 4) == 0) { a0 += pp; c0 += ss; }
        else                 { a1 += pp; c1 += ss; }
    }
    #pragma unroll
    for (int off = 16; off; off >>= 1) {
        a0 += __shfl_down_sync(FULLM, a0, off);
        c0 += __shfl_down_sync(FULLM, c0, off);
        a1 += __shfl_down_sync(FULLM, a1, off);
        c1 += __shfl_down_sync(FULLM, c1, off);
    }
    const int lane = threadIdx.x & 31, w = threadIdx.x >> 5;
    if (lane == 0) { sp0[w] = a0; ss0[w] = c0; sp1[w] = a1; ss1[w] = c1; }
    __syncthreads();
    if (threadIdx.x == 0) {
        double P0 = 0, S0 = 0, P1 = 0, S1 = 0;
        #pragma unroll
        for (int i = 0; i < 8; i++) { P0 += sp0[i]; S0 += ss0[i]; P1 += sp1[i]; S1 += ss1[i]; }
        double iflat = (P0 + 1.0) / (S0 + 1.0);   // sum(skelP*gt)/sum(skelP)
        double tflat = (P1 + 1.0) / (S1 + 1.0);   // sum(skelG*pred)/sum(skelG)
        out[0] = (float)(1.0 - 2.0 * iflat * tflat / (iflat + tflat));
    }
}

extern "C" void kernel_launch(void* const* d_in, const int* in_sizes, int n_in,
                              void* d_out, int out_size)
{
    const float* pred = (const float*)d_in[0];
    const float* gt   = (const float*)d_in[1];
    float* out = (float*)d_out;

    float *b0 = 0, *b1 = 0;
    cudaGetSymbolAddress((void**)&b0, g_buf0);
    cudaGetSymbolAddress((void**)&b1, g_buf1);

    dim3 grid(NBAND, 2, 2 * BATCH);   // (16, 2, 32) = 1024 blocks of 128 thr
    const int threads = 128;

    // Iteration 0 reads the harness inputs.
    skel_kernel<false><<<grid, threads>>>(pred, gt, b0, (const float*)0, (const float*)0);

    // Iterations 1..18 ping-pong scratch.
    float* cur = b0;
    float* nxt = b1;
    for (int i = 1; i < 19; i++) {
        skel_kernel<false><<<grid, threads>>>(cur, cur + NTEN, nxt, (const float*)0, (const float*)0);
        float* tmp = cur; cur = nxt; nxt = tmp;
    }

    // Iteration 19 fused with the reductions.
    skel_kernel<true><<<grid, threads>>>(cur, cur + NTEN, (float*)0, gt, pred);

    finish_kernel<<<1, 256>>>(out);
}

// round 16
// speedup vs baseline: 1.1936x; 1.1936x over previous
#include <cuda_runtime.h>
#include <cstdint>

#define HH 1024
#define WW 1024
#define BATCH 16
#define NIMG (HH*WW)
#define NTEN (BATCH*NIMG)
#define RS 64                       // output rows per warp sweep
#define NBAND (HH/RS)               // 16
#define DEPTH 8                     // cp.async ring stages per warp
#define FULLM 0xffffffffu
#define TOTW 4096                   // 8 strips * 16 bands * 32 images

__device__ float g_buf0[2*NTEN];
__device__ float g_buf1[2*NTEN];
__device__ double g_pp[TOTW];
__device__ double g_ps[TOTW];

__device__ __forceinline__ float PINF() { return __int_as_float(0x7f800000); }
__device__ __forceinline__ float NINF() { return __int_as_float(0xff800000); }
__device__ __forceinline__ float min3(float a, float b, float c) { return fminf(a, fminf(b, c)); }
__device__ __forceinline__ float max3(float a, float b, float c) { return fmaxf(a, fmaxf(b, c)); }

__device__ __forceinline__ uint32_t saddr(const void* p) {
    return (uint32_t)__cvta_generic_to_shared(p);
}
__device__ __forceinline__ void cp16(uint32_t s, const void* g) {
    asm volatile("cp.async.cg.shared.global [%0], [%1], 16;" :: "r"(s), "l"(g));
}
__device__ __forceinline__ void cp8(uint32_t s, const void* g) {
    asm volatile("cp.async.ca.shared.global [%0], [%1], 8;" :: "r"(s), "l"(g));
}
__device__ __forceinline__ void cp_commit() {
    asm volatile("cp.async.commit_group;" ::: "memory");
}
template<int N>
__device__ __forceinline__ void cp_wait() {
    asm volatile("cp.async.wait_group %0;" :: "n"(N) : "memory");
}

// Rolling state for the separable 3x3 min-pool -> 3x3 max-pool pipeline.
struct St {
    float hA[4], hB[4];      // horizontal-min rows (rr-2, rr-1)
    float gA[4], gB[4];      // vertical-max candidate rows
    float mC[4];             // min-pool value at the output row (unmasked)
    float hlA, hlB, hrA, hrB;// edge-lane horizontal mins (left/right halo)
    float4 xA, xB;           // input delay line (x at output row)
};

__device__ __forceinline__ void st_init(St& S) {
    #pragma unroll
    for (int j = 0; j < 4; j++) {
        S.hA[j] = PINF(); S.hB[j] = PINF();
        S.gA[j] = NINF(); S.gB[j] = NINF();
        S.mC[j] = 0.f;
    }
    S.hlA = PINF(); S.hlB = PINF(); S.hrA = PINF(); S.hrB = PINF();
    S.xA = make_float4(0.f, 0.f, 0.f, 0.f);
    S.xB = S.xA;
}

// Process one input row; emit skeleton output for row rr-2.
template<bool VEDGE>
__device__ __forceinline__ float4 advance(St& S, int lane, int rr,
                                          bool leftok, bool rightok,
                                          float4 A, float xl2, float xl1,
                                          float xr0, float xr1)
{
    float xm1 = __shfl_up_sync(FULLM, A.w, 1);
    if (lane == 0) xm1 = xl1;
    float xp4 = __shfl_down_sync(FULLM, A.x, 1);
    if (lane == 31) xp4 = xr0;
    float hC[4];
    hC[0] = min3(xm1, A.x, A.y);  hC[1] = min3(A.x, A.y, A.z);
    hC[2] = min3(A.y, A.z, A.w);  hC[3] = min3(A.z, A.w, xp4);
    float hlC = min3(xl2, xl1, A.x);
    float hrC = min3(A.w, xr0, xr1);

    float m[4], mM[4];
    const bool rvC = (!VEDGE) || (((rr - 1) >= 0) && ((rr - 1) < HH));
    #pragma unroll
    for (int j = 0; j < 4; j++) {
        m[j]  = min3(S.hA[j], S.hB[j], hC[j]);
        mM[j] = rvC ? m[j] : NINF();
    }
    float ml = min3(S.hlA, S.hlB, hlC);
    float mr = min3(S.hrA, S.hrB, hrC);
    float mlM = (leftok  && rvC) ? ml : NINF();
    float mrM = (rightok && rvC) ? mr : NINF();

    float mm1 = __shfl_up_sync(FULLM, mM[3], 1);
    if (lane == 0) mm1 = mlM;
    float mp4 = __shfl_down_sync(FULLM, mM[0], 1);
    if (lane == 31) mp4 = mrM;
    float gC[4];
    gC[0] = max3(mm1,  mM[0], mM[1]);  gC[1] = max3(mM[0], mM[1], mM[2]);
    gC[2] = max3(mM[1], mM[2], mM[3]); gC[3] = max3(mM[2], mM[3], mp4);

    float4 o;
    o.x = fmaxf(S.xA.x - fmaxf(max3(S.gA[0], S.gB[0], gC[0]) - S.mC[0], 0.f), 0.f);
    o.y = fmaxf(S.xA.y - fmaxf(max3(S.gA[1], S.gB[1], gC[1]) - S.mC[1], 0.f), 0.f);
    o.z = fmaxf(S.xA.z - fmaxf(max3(S.gA[2], S.gB[2], gC[2]) - S.mC[2], 0.f), 0.f);
    o.w = fmaxf(S.xA.w - fmaxf(max3(S.gA[3], S.gB[3], gC[3]) - S.mC[3], 0.f), 0.f);

    #pragma unroll
    for (int j = 0; j < 4; j++) {
        S.hA[j] = S.hB[j]; S.hB[j] = hC[j];
        S.gA[j] = S.gB[j]; S.gB[j] = gC[j];
        S.mC[j] = m[j];
    }
    S.hlA = S.hlB; S.hlB = hlC;
    S.hrA = S.hrB; S.hrB = hrC;
    S.xA = S.xB; S.xB = A;
    return o;
}

// Prefetch input row rr into ring stage s; one commit group per row.
// CLAMP (edge bands only): clamp the row index into the image. Interior bands
// compile without the clamp — all prefetched rows are provably in-image.
template<bool CLAMP>
__device__ __forceinline__ void prefetch(const float* __restrict__ src, int rr,
                                         int gX, int c0, int lane,
                                         bool leftok, bool rightok,
                                         float4* ringw, float2* hlw, float2* hrw,
                                         int s)
{
    int rc = rr;
    if (CLAMP) rc = rr < 0 ? 0 : (rr > HH - 1 ? HH - 1 : rr);
    const float* rowp = src + (long)rc * WW;
    cp16(saddr(ringw + s * 32 + lane), rowp + gX);
    if (lane == 0 && leftok)   cp8(saddr(hlw + s), rowp + c0 - 2);
    if (lane == 31 && rightok) cp8(saddr(hrw + s), rowp + c0 + 128);
    cp_commit();
}

template<bool VEDGE, bool FINAL>
__device__ __forceinline__ void sweep(const float* __restrict__ src,
                                      float* __restrict__ out,
                                      const float* __restrict__ oth,
                                      int c0, int gX, int r0, int lane,
                                      bool leftok, bool rightok,
                                      float4* ringw, float2* hlw, float2* hrw,
                                      float& accp, float& accs)
{
    St S;
    st_init(S);

    // Halo slot defaults (+inf). Lane 0 owns hlw, lane 31 owns hrw; a slot is
    // only ever read back by the thread that wrote it (cross-lane halo values
    // travel via shuffles inside advance()).
    if (lane == 0) {
        #pragma unroll
        for (int s = 0; s < DEPTH; s++) hlw[s] = make_float2(PINF(), PINF());
    }
    if (lane == 31) {
        #pragma unroll
        for (int s = 0; s < DEPTH; s++) hrw[s] = make_float2(PINF(), PINF());
    }

    // Fill the ring: rows r0-2 .. r0-2+DEPTH-1.
    #pragma unroll
    for (int s = 0; s < DEPTH; s++)
        prefetch<VEDGE>(src, r0 - 2 + s, gX, c0, lane, leftok, rightok, ringw, hlw, hrw, s);

    // Prologue: rows r0-2 .. r0+1 (fill compute pipeline, no emit).
    #pragma unroll
    for (int k = 0; k < 4; k++) {
        const int rr = r0 - 2 + k;
        const int s  = k & (DEPTH - 1);
        cp_wait<DEPTH - 1>();
        float4 A  = ringw[s * 32 + lane];
        float2 hl = hlw[s];
        float2 hr = hrw[s];
        if (VEDGE && !((rr >= 0) && (rr < HH))) {
            A  = make_float4(PINF(), PINF(), PINF(), PINF());
            hl = make_float2(PINF(), PINF());
            hr = make_float2(PINF(), PINF());
        }
        (void)advance<VEDGE>(S, lane, rr, leftok, rightok, A, hl.x, hl.y, hr.x, hr.y);
        prefetch<VEDGE>(src, rr + DEPTH, gX, c0, lane, leftok, rightok, ringw, hlw, hrw, s);
    }

    // Main: rows r0+2 .. r0+RS+1 -> emit rows r0 .. r0+RS-1.
    #pragma unroll 8
    for (int k = 0; k < RS; k++) {
        const int rr = r0 + 2 + k;
        const int s  = (k + 4) & (DEPTH - 1);
        cp_wait<DEPTH - 1>();
        float4 A  = ringw[s * 32 + lane];
        float2 hl = hlw[s];
        float2 hr = hrw[s];
        if (VEDGE && !((rr >= 0) && (rr < HH))) {
            A  = make_float4(PINF(), PINF(), PINF(), PINF());
            hl = make_float2(PINF(), PINF());
            hr = make_float2(PINF(), PINF());
        }
        float4 o = advance<VEDGE>(S, lane, rr, leftok, rightok, A, hl.x, hl.y, hr.x, hr.y);
        const int orow = r0 + k;
        if (FINAL) {
            const float4 ov = __ldcs((const float4*)(oth + ((long)orow * WW + gX)));
            accp += o.x * ov.x + o.y * ov.y + o.z * ov.z + o.w * ov.w;
            accs += o.x + o.y + o.z + o.w;
        } else {
            __stcs((float4*)(out + ((long)orow * WW + gX)), o);
        }
        // Refill the slot just consumed.
        prefetch<VEDGE>(src, rr + DEPTH, gX, c0, lane, leftok, rightok, ringw, hlw, hrw, s);
    }
    cp_wait<0>();
}

template<bool FINAL>
__global__ __launch_bounds__(128, 8)
void skel_kernel(const float* __restrict__ in0, const float* __restrict__ in1,
                 float* __restrict__ dst,
                 const float* __restrict__ oth0, const float* __restrict__ oth1)
{
    __shared__ float4 ring[4][DEPTH * 32];   // 16 KB: [warp][stage*32+lane]
    __shared__ float2 haloL[4][DEPTH];
    __shared__ float2 haloR[4][DEPTH];

    const int lane  = threadIdx.x & 31;
    const int warp  = threadIdx.x >> 5;
    const int strip = blockIdx.y * 4 + warp;      // 0..7 (128 cols each)
    const int band  = blockIdx.x;                 // 0..15
    const int img   = blockIdx.z;                 // 0..31
    const int t = img >> 4;
    const int b = img & 15;

    const float* src = (t == 0 ? in0 : in1) + (size_t)b * NIMG;
    const float* oth = FINAL ? ((t == 0 ? oth0 : oth1) + (size_t)b * NIMG) : (const float*)0;
    float* out = FINAL ? (float*)0 : dst + (size_t)t * NTEN + (size_t)b * NIMG;

    const int c0 = strip * 128;
    const int gX = c0 + 4 * lane;
    const int r0 = band * RS;
    const bool leftok  = (strip > 0);
    const bool rightok = (strip < 7);

    float accp = 0.f, accs = 0.f;
    if (band == 0 || band == NBAND - 1)
        sweep<true,  FINAL>(src, out, oth, c0, gX, r0, lane, leftok, rightok,
                            ring[warp], haloL[warp], haloR[warp], accp, accs);
    else
        sweep<false, FINAL>(src, out, oth, c0, gX, r0, lane, leftok, rightok,
                            ring[warp], haloL[warp], haloR[warp], accp, accs);

    if (FINAL) {
        double p = (double)accp, s = (double)accs;
        #pragma unroll
        for (int off = 16; off; off >>= 1) {
            p += __shfl_down_sync(FULLM, p, off);
            s += __shfl_down_sync(FULLM, s, off);
        }
        if (lane == 0) {
            const int wid = (img * NBAND + band) * 8 + strip;
            g_pp[wid] = p;
            g_ps[wid] = s;
        }
    }
}

__global__ void finish_kernel(float* __restrict__ out)
{
    __shared__ double sp0[8], ss0[8], sp1[8], ss1[8];
    double a0 = 0, c0 = 0, a1 = 0, c1 = 0;
    for (int i = threadIdx.x; i < TOTW; i += 256) {
        const int img = i >> 7;     // 128 warps per image
        double pp = g_pp[i], ss = g_ps[i];
        if ((img >> 4) == 0) { a0 += pp; c0 += ss; }
        else                 { a1 += pp; c1 += ss; }
    }
    #pragma unroll
    for (int off = 16; off; off >>= 1) {
        a0 += __shfl_down_sync(FULLM, a0, off);
        c0 += __shfl_down_sync(FULLM, c0, off);
        a1 += __shfl_down_sync(FULLM, a1, off);
        c1 += __shfl_down_sync(FULLM, c1, off);
    }
    const int lane = threadIdx.x & 31, w = threadIdx.x >> 5;
    if (lane == 0) { sp0[w] = a0; ss0[w] = c0; sp1[w] = a1; ss1[w] = c1; }
    __syncthreads();
    if (threadIdx.x == 0) {
        double P0 = 0, S0 = 0, P1 = 0, S1 = 0;
        #pragma unroll
        for (int i = 0; i < 8; i++) { P0 += sp0[i]; S0 += ss0[i]; P1 += sp1[i]; S1 += ss1[i]; }
        double iflat = (P0 + 1.0) / (S0 + 1.0);   // sum(skelP*gt)/sum(skelP)
        double tflat = (P1 + 1.0) / (S1 + 1.0);   // sum(skelG*pred)/sum(skelG)
        out[0] = (float)(1.0 - 2.0 * iflat * tflat / (iflat + tflat));
    }
}

extern "C" void kernel_launch(void* const* d_in, const int* in_sizes, int n_in,
                              void* d_out, int out_size)
{
    const float* pred = (const float*)d_in[0];
    const float* gt   = (const float*)d_in[1];
    float* out = (float*)d_out;

    float *b0 = 0, *b1 = 0;
    cudaGetSymbolAddress((void**)&b0, g_buf0);
    cudaGetSymbolAddress((void**)&b1, g_buf1);

    dim3 grid(NBAND, 2, 2 * BATCH);   // (16, 2, 32) = 1024 blocks of 128 thr
    const int threads = 128;

    // Iteration 0 reads the harness inputs.
    skel_kernel<false><<<grid, threads>>>(pred, gt, b0, (const float*)0, (const float*)0);

    // Iterations 1..18 ping-pong scratch.
    float* cur = b0;
    float* nxt = b1;
    for (int i = 1; i < 19; i++) {
        skel_kernel<false><<<grid, threads>>>(cur, cur + NTEN, nxt, (const float*)0, (const float*)0);
        float* tmp = cur; cur = nxt; nxt = tmp;
    }

    // Iteration 19 fused with the reductions.
    skel_kernel<true><<<grid, threads>>>(cur, cur + NTEN, (float*)0, gt, pred);

    finish_kernel<<<1, 256>>>(out);
}

// round 17
// speedup vs baseline: 1.1983x; 1.0040x over previous
#include <cuda_runtime.h>
#include <cstdint>

#define HH 1024
#define WW 1024
#define BATCH 16
#define NIMG (HH*WW)
#define NTEN (BATCH*NIMG)
#define RS 64                       // output rows per warp sweep
#define NBAND (HH/RS)               // 16
#define DEPTH 8                     // cp.async ring stages per warp
#define FULLM 0xffffffffu
#define TOTW 4096                   // 8 strips * 16 bands * 32 images

__device__ float g_buf0[2*NTEN];
__device__ float g_buf1[2*NTEN];
__device__ double g_pp[TOTW];
__device__ double g_ps[TOTW];

__device__ __forceinline__ float PINF() { return __int_as_float(0x7f800000); }
__device__ __forceinline__ float NINF() { return __int_as_float(0xff800000); }
__device__ __forceinline__ float min3(float a, float b, float c) { return fminf(a, fminf(b, c)); }
__device__ __forceinline__ float max3(float a, float b, float c) { return fmaxf(a, fmaxf(b, c)); }

__device__ __forceinline__ uint32_t saddr(const void* p) {
    return (uint32_t)__cvta_generic_to_shared(p);
}
__device__ __forceinline__ void cp16(uint32_t s, const void* g) {
    asm volatile("cp.async.cg.shared.global [%0], [%1], 16;" :: "r"(s), "l"(g));
}
__device__ __forceinline__ void cp8(uint32_t s, const void* g) {
    asm volatile("cp.async.ca.shared.global [%0], [%1], 8;" :: "r"(s), "l"(g));
}
__device__ __forceinline__ void cp_commit() {
    asm volatile("cp.async.commit_group;" ::: "memory");
}
template<int N>
__device__ __forceinline__ void cp_wait() {
    asm volatile("cp.async.wait_group %0;" :: "n"(N) : "memory");
}

// Rolling state for the separable 3x3 min-pool -> 3x3 max-pool pipeline.
struct St {
    float hA[4], hB[4];      // horizontal-min rows (rr-2, rr-1)
    float gA[4], gB[4];      // vertical-max candidate rows
    float mC[4];             // min-pool value at the output row (unmasked)
    float hlA, hlB, hrA, hrB;// edge-lane horizontal mins (left/right halo)
    float4 xA, xB;           // input delay line (x at output row)
};

__device__ __forceinline__ void st_init(St& S) {
    #pragma unroll
    for (int j = 0; j < 4; j++) {
        S.hA[j] = PINF(); S.hB[j] = PINF();
        S.gA[j] = NINF(); S.gB[j] = NINF();
        S.mC[j] = 0.f;
    }
    S.hlA = PINF(); S.hlB = PINF(); S.hrA = PINF(); S.hrB = PINF();
    S.xA = make_float4(0.f, 0.f, 0.f, 0.f);
    S.xB = S.xA;
}

// Process one input row; emit skeleton output for row rr-2.
template<bool VEDGE>
__device__ __forceinline__ float4 advance(St& S, int lane, int rr,
                                          bool leftok, bool rightok,
                                          float4 A, float xl2, float xl1,
                                          float xr0, float xr1)
{
    float xm1 = __shfl_up_sync(FULLM, A.w, 1);
    if (lane == 0) xm1 = xl1;
    float xp4 = __shfl_down_sync(FULLM, A.x, 1);
    if (lane == 31) xp4 = xr0;
    float hC[4];
    hC[0] = min3(xm1, A.x, A.y);  hC[1] = min3(A.x, A.y, A.z);
    hC[2] = min3(A.y, A.z, A.w);  hC[3] = min3(A.z, A.w, xp4);
    float hlC = min3(xl2, xl1, A.x);
    float hrC = min3(A.w, xr0, xr1);

    float m[4], mM[4];
    const bool rvC = (!VEDGE) || (((rr - 1) >= 0) && ((rr - 1) < HH));
    #pragma unroll
    for (int j = 0; j < 4; j++) {
        m[j]  = min3(S.hA[j], S.hB[j], hC[j]);
        mM[j] = rvC ? m[j] : NINF();
    }
    float ml = min3(S.hlA, S.hlB, hlC);
    float mr = min3(S.hrA, S.hrB, hrC);
    float mlM = (leftok  && rvC) ? ml : NINF();
    float mrM = (rightok && rvC) ? mr : NINF();

    float mm1 = __shfl_up_sync(FULLM, mM[3], 1);
    if (lane == 0) mm1 = mlM;
    float mp4 = __shfl_down_sync(FULLM, mM[0], 1);
    if (lane == 31) mp4 = mrM;
    float gC[4];
    gC[0] = max3(mm1,  mM[0], mM[1]);  gC[1] = max3(mM[0], mM[1], mM[2]);
    gC[2] = max3(mM[1], mM[2], mM[3]); gC[3] = max3(mM[2], mM[3], mp4);

    float4 o;
    o.x = fmaxf(S.xA.x - fmaxf(max3(S.gA[0], S.gB[0], gC[0]) - S.mC[0], 0.f), 0.f);
    o.y = fmaxf(S.xA.y - fmaxf(max3(S.gA[1], S.gB[1], gC[1]) - S.mC[1], 0.f), 0.f);
    o.z = fmaxf(S.xA.z - fmaxf(max3(S.gA[2], S.gB[2], gC[2]) - S.mC[2], 0.f), 0.f);
    o.w = fmaxf(S.xA.w - fmaxf(max3(S.gA[3], S.gB[3], gC[3]) - S.mC[3], 0.f), 0.f);

    #pragma unroll
    for (int j = 0; j < 4; j++) {
        S.hA[j] = S.hB[j]; S.hB[j] = hC[j];
        S.gA[j] = S.gB[j]; S.gB[j] = gC[j];
        S.mC[j] = m[j];
    }
    S.hlA = S.hlB; S.hlB = hlC;
    S.hrA = S.hrB; S.hrB = hrC;
    S.xA = S.xB; S.xB = A;
    return o;
}

// Prefetch input row rr into ring stage s; one commit group per row.
template<bool CLAMP>
__device__ __forceinline__ void prefetch(const float* __restrict__ src, int rr,
                                         int gX, int c0, int lane,
                                         bool leftok, bool rightok,
                                         float4* ringw, float2* hlw, float2* hrw,
                                         int s)
{
    int rc = rr;
    if (CLAMP) rc = rr < 0 ? 0 : (rr > HH - 1 ? HH - 1 : rr);
    const float* rowp = src + (long)rc * WW;
    cp16(saddr(ringw + s * 32 + lane), rowp + gX);
    if (lane == 0 && leftok)   cp8(saddr(hlw + s), rowp + c0 - 2);
    if (lane == 31 && rightok) cp8(saddr(hrw + s), rowp + c0 + 128);
    cp_commit();
}

// Read ring stage s for row rr into registers (masked to +inf if outside image).
template<bool VEDGE>
__device__ __forceinline__ void stage_read(const float4* ringw, const float2* hlw,
                                           const float2* hrw, int s, int rr, int lane,
                                           float4& A, float2& hl, float2& hr)
{
    A  = ringw[s * 32 + lane];
    hl = hlw[s];
    hr = hrw[s];
    if (VEDGE && !((rr >= 0) && (rr < HH))) {
        A  = make_float4(PINF(), PINF(), PINF(), PINF());
        hl = make_float2(PINF(), PINF());
        hr = make_float2(PINF(), PINF());
    }
}

template<bool VEDGE, bool FINAL>
__device__ __forceinline__ void sweep(const float* __restrict__ src,
                                      float* __restrict__ out,
                                      const float* __restrict__ oth,
                                      int c0, int gX, int r0, int lane,
                                      bool leftok, bool rightok,
                                      float4* ringw, float2* hlw, float2* hrw,
                                      float& accp, float& accs)
{
    St S;
    st_init(S);

    // Halo slot defaults (+inf). Lane 0 owns hlw, lane 31 owns hrw; each slot
    // is only read back by the thread that wrote it.
    if (lane == 0) {
        #pragma unroll
        for (int s = 0; s < DEPTH; s++) hlw[s] = make_float2(PINF(), PINF());
    }
    if (lane == 31) {
        #pragma unroll
        for (int s = 0; s < DEPTH; s++) hrw[s] = make_float2(PINF(), PINF());
    }

    // Fill the ring: rows r0-2 .. r0+5 (8 groups).
    #pragma unroll
    for (int s = 0; s < DEPTH; s++)
        prefetch<VEDGE>(src, r0 - 2 + s, gX, c0, lane, leftok, rightok, ringw, hlw, hrw, s);

    // Stage row r0-2 (slot 0). After 8 commits, wait<6> guarantees >=2 groups
    // landed; throughout the loop, wait<6> at iteration j (8+j commits total)
    // guarantees rows up to j+1 are landed — i.e. the row staged for NEXT
    // iteration is ready.
    float4 Ac;  float2 hlc, hrc;
    cp_wait<DEPTH - 2>();
    stage_read<VEDGE>(ringw, hlw, hrw, 0, r0 - 2, lane, Ac, hlc, hrc);

    // Prologue: rows r0-2 .. r0+1 (fill compute pipeline, no emit).
    #pragma unroll
    for (int k = 0; k < 4; k++) {
        const int rr = r0 - 2 + k;
        const int s  = k & (DEPTH - 1);
        (void)advance<VEDGE>(S, lane, rr, leftok, rightok, Ac, hlc.x, hlc.y, hrc.x, hrc.y);
        prefetch<VEDGE>(src, rr + DEPTH, gX, c0, lane, leftok, rightok, ringw, hlw, hrw, s);
        cp_wait<DEPTH - 2>();
        stage_read<VEDGE>(ringw, hlw, hrw, (s + 1) & (DEPTH - 1), rr + 1, lane, Ac, hlc, hrc);
    }

    // Main: rows r0+2 .. r0+RS+1 -> emit rows r0 .. r0+RS-1.
    #pragma unroll 8
    for (int k = 0; k < RS; k++) {
        const int rr = r0 + 2 + k;
        const int s  = (k + 4) & (DEPTH - 1);
        float4 o = advance<VEDGE>(S, lane, rr, leftok, rightok, Ac, hlc.x, hlc.y, hrc.x, hrc.y);
        const int orow = r0 + k;
        if (FINAL) {
            const float4 ov = __ldcs((const float4*)(oth + ((long)orow * WW + gX)));
            accp += o.x * ov.x + o.y * ov.y + o.z * ov.z + o.w * ov.w;
            accs += o.x + o.y + o.z + o.w;
        } else {
            __stcs((float4*)(out + ((long)orow * WW + gX)), o);
        }
        // Refill the slot just consumed, then stage the next row.
        prefetch<VEDGE>(src, rr + DEPTH, gX, c0, lane, leftok, rightok, ringw, hlw, hrw, s);
        cp_wait<DEPTH - 2>();
        stage_read<VEDGE>(ringw, hlw, hrw, (s + 1) & (DEPTH - 1), rr + 1, lane, Ac, hlc, hrc);
    }
    cp_wait<0>();
}

template<bool FINAL>
__global__ __launch_bounds__(128)
void skel_kernel(const float* __restrict__ in0, const float* __restrict__ in1,
                 float* __restrict__ dst,
                 const float* __restrict__ oth0, const float* __restrict__ oth1)
{
    __shared__ float4 ring[4][DEPTH * 32];   // 16 KB: [warp][stage*32+lane]
    __shared__ float2 haloL[4][DEPTH];
    __shared__ float2 haloR[4][DEPTH];

    const int lane  = threadIdx.x & 31;
    const int warp  = threadIdx.x >> 5;
    const int strip = blockIdx.y * 4 + warp;      // 0..7 (128 cols each)
    const int band  = blockIdx.x;                 // 0..15
    const int img   = blockIdx.z;                 // 0..31
    const int t = img >> 4;
    const int b = img & 15;

    const float* src = (t == 0 ? in0 : in1) + (size_t)b * NIMG;
    const float* oth = FINAL ? ((t == 0 ? oth0 : oth1) + (size_t)b * NIMG) : (const float*)0;
    float* out = FINAL ? (float*)0 : dst + (size_t)t * NTEN + (size_t)b * NIMG;

    const int c0 = strip * 128;
    const int gX = c0 + 4 * lane;
    const int r0 = band * RS;
    const bool leftok  = (strip > 0);
    const bool rightok = (strip < 7);

    float accp = 0.f, accs = 0.f;
    if (band == 0 || band == NBAND - 1)
        sweep<true,  FINAL>(src, out, oth, c0, gX, r0, lane, leftok, rightok,
                            ring[warp], haloL[warp], haloR[warp], accp, accs);
    else
        sweep<false, FINAL>(src, out, oth, c0, gX, r0, lane, leftok, rightok,
                            ring[warp], haloL[warp], haloR[warp], accp, accs);

    if (FINAL) {
        double p = (double)accp, s = (double)accs;
        #pragma unroll
        for (int off = 16; off; off >>= 1) {
            p += __shfl_down_sync(FULLM, p, off);
            s += __shfl_down_sync(FULLM, s, off);
        }
        if (lane == 0) {
            const int wid = (img * NBAND + band) * 8 + strip;
            g_pp[wid] = p;
            g_ps[wid] = s;
        }
    }
}

__global__ void finish_kernel(float* __restrict__ out)
{
    __shared__ double sp0[8], ss0[8], sp1[8], ss1[8];
    double a0 = 0, c0 = 0, a1 = 0, c1 = 0;
    for (int i = threadIdx.x; i < TOTW; i += 256) {
        const int img = i >> 7;     // 128 warps per image
        double pp = g_pp[i], ss = g_ps[i];
        if ((img >> 4) == 0) { a0 += pp; c0 += ss; }
        else                 { a1 += pp; c1 += ss; }
    }
    #pragma unroll
    for (int off = 16; off; off >>= 1) {
        a0 += __shfl_down_sync(FULLM, a0, off);
        c0 += __shfl_down_sync(FULLM, c0, off);
        a1 += __shfl_down_sync(FULLM, a1, off);
        c1 += __shfl_down_sync(FULLM, c1, off);
    }
    const int lane = threadIdx.x & 31, w = threadIdx.x >> 5;
    if (lane == 0) { sp0[w] = a0; ss0[w] = c0; sp1[w] = a1; ss1[w] = c1; }
    __syncthreads();
    if (threadIdx.x == 0) {
        double P0 = 0, S0 = 0, P1 = 0, S1 = 0;
        #pragma unroll
        for (int i = 0; i < 8; i++) { P0 += sp0[i]; S0 += ss0[i]; P1 += sp1[i]; S1 += ss1[i]; }
        double iflat = (P0 + 1.0) / (S0 + 1.0);   // sum(skelP*gt)/sum(skelP)
        double tflat = (P1 + 1.0) / (S1 + 1.0);   // sum(skelG*pred)/sum(skelG)
        out[0] = (float)(1.0 - 2.0 * iflat * tflat / (iflat + tflat));
    }
}

extern "C" void kernel_launch(void* const* d_in, const int* in_sizes, int n_in,
                              void* d_out, int out_size)
{
    const float* pred = (const float*)d_in[0];
    const float* gt   = (const float*)d_in[1];
    float* out = (float*)d_out;

    float *b0 = 0, *b1 = 0;
    cudaGetSymbolAddress((void**)&b0, g_buf0);
    cudaGetSymbolAddress((void**)&b1, g_buf1);

    dim3 grid(NBAND, 2, 2 * BATCH);   // (16, 2, 32) = 1024 blocks of 128 thr
    const int threads = 128;

    // Iteration 0 reads the harness inputs.
    skel_kernel<false><<<grid, threads>>>(pred, gt, b0, (const float*)0, (const float*)0);

    // Iterations 1..18 ping-pong scratch.
    float* cur = b0;
    float* nxt = b1;
    for (int i = 1; i < 19; i++) {
        skel_kernel<false><<<grid, threads>>>(cur, cur + NTEN, nxt, (const float*)0, (const float*)0);
        float* tmp = cur; cur = nxt; nxt = tmp;
    }

    // Iteration 19 fused with the reductions.
    skel_kernel<true><<<grid, threads>>>(cur, cur + NTEN, (float*)0, gt, pred);

    finish_kernel<<<1, 256>>>(out);
}